// round 1
// baseline (speedup 1.0000x reference)
#include <cuda_runtime.h>
#include <cstdint>

#define D_MODEL 1024
#define N_SEQ   1024
#define B_BATCH 4
#define H_HEADS 16
// DK = 64

// ---------------- scratch (static device globals; no runtime allocation) ----------------
__device__ float g_q[(size_t)B_BATCH * D_MODEL * N_SEQ];
__device__ float g_k[(size_t)B_BATCH * D_MODEL * N_SEQ];
__device__ float g_v[(size_t)B_BATCH * D_MODEL * N_SEQ];
__device__ float g_a[(size_t)B_BATCH * D_MODEL * N_SEQ];
__device__ float g_m[(size_t)B_BATCH * D_MODEL * N_SEQ];
__device__ float g_h[(size_t)B_BATCH * 2 * D_MODEL * N_SEQ];
__device__ float g_x[(size_t)B_BATCH * D_MODEL * N_SEQ];

// ---------------------------------------------------------------------------------------
// Batched GEMM:  Y[b] = W (Co x Ci) @ X[b] (Ci x N) + bias, with epilogues.
//   EPI 0: Y = WX + bias
//   EPI 1: Y = relu( bn_g * (WX + bias - bn_mu) * rsqrt(bn_var+eps) + bn_b )
//   EPI 2: Y = WX + bias + res
// Input X is logically the concat of X0 (rows0 channels) then X1 (Ci-rows0 channels).
// Tiles: 128x128x16, 256 threads, 8x8 per-thread microtile. All dims multiples of tile.
// ---------------------------------------------------------------------------------------
template<int EPI>
__global__ __launch_bounds__(256)
void gemm_k(const float* __restrict__ W, const float* __restrict__ bias,
            const float* __restrict__ X0, int rows0,
            const float* __restrict__ X1,
            const float* __restrict__ bng, const float* __restrict__ bnb,
            const float* __restrict__ bnm, const float* __restrict__ bnv,
            const float* __restrict__ res,
            float* __restrict__ Y, int Co, int Ci)
{
    __shared__ float As[16][128];   // As[k][co]
    __shared__ float Bs[16][128];   // Bs[k][n]

    const int t   = threadIdx.x;
    const int tx  = t & 15;
    const int ty  = t >> 4;
    const int b   = blockIdx.z;
    const int bm0 = blockIdx.y * 128;
    const int bn0 = blockIdx.x * 128;

    // A (weight) loader: thread -> (co = t>>1, k half = (t&1)*8), 2x float4
    const int a_co = t >> 1;
    const int a_k  = (t & 1) * 8;
    const float* wrow = W + (size_t)(bm0 + a_co) * Ci + a_k;

    // B (activation) loader: two float4 per thread: rows bk0 and bk0+8, cols bc..bc+3
    const int bk0 = t >> 5;          // 0..7
    const int bc  = (t & 31) * 4;    // 0..124
    const int rows1 = Ci - rows0;

    float acc[8][8];
#pragma unroll
    for (int i = 0; i < 8; ++i)
#pragma unroll
        for (int j = 0; j < 8; ++j) acc[i][j] = 0.f;

    float4 ra0, ra1, rb0, rb1;

    // prologue loads (kt = 0)
    {
        ra0 = *(const float4*)(wrow);
        ra1 = *(const float4*)(wrow + 4);
        int ci0 = bk0;
        const float* s0 = (ci0 < rows0)
            ? (X0 + ((size_t)b * rows0 + ci0) * N_SEQ)
            : (X1 + ((size_t)b * rows1 + (ci0 - rows0)) * N_SEQ);
        rb0 = *(const float4*)(s0 + bn0 + bc);
        int ci1 = bk0 + 8;
        const float* s1 = (ci1 < rows0)
            ? (X0 + ((size_t)b * rows0 + ci1) * N_SEQ)
            : (X1 + ((size_t)b * rows1 + (ci1 - rows0)) * N_SEQ);
        rb1 = *(const float4*)(s1 + bn0 + bc);
    }

    for (int kt = 0; kt < Ci; kt += 16) {
        __syncthreads();
        // store staged tiles to smem (A transposed)
        As[a_k + 0][a_co] = ra0.x;
        As[a_k + 1][a_co] = ra0.y;
        As[a_k + 2][a_co] = ra0.z;
        As[a_k + 3][a_co] = ra0.w;
        As[a_k + 4][a_co] = ra1.x;
        As[a_k + 5][a_co] = ra1.y;
        As[a_k + 6][a_co] = ra1.z;
        As[a_k + 7][a_co] = ra1.w;
        *(float4*)&Bs[bk0][bc]     = rb0;
        *(float4*)&Bs[bk0 + 8][bc] = rb1;
        __syncthreads();

        // prefetch next tile while computing
        if (kt + 16 < Ci) {
            ra0 = *(const float4*)(wrow + kt + 16);
            ra1 = *(const float4*)(wrow + kt + 16 + 4);
            int ci0 = kt + 16 + bk0;
            const float* s0 = (ci0 < rows0)
                ? (X0 + ((size_t)b * rows0 + ci0) * N_SEQ)
                : (X1 + ((size_t)b * rows1 + (ci0 - rows0)) * N_SEQ);
            rb0 = *(const float4*)(s0 + bn0 + bc);
            int ci1 = ci0 + 8;
            const float* s1 = (ci1 < rows0)
                ? (X0 + ((size_t)b * rows0 + ci1) * N_SEQ)
                : (X1 + ((size_t)b * rows1 + (ci1 - rows0)) * N_SEQ);
            rb1 = *(const float4*)(s1 + bn0 + bc);
        }

#pragma unroll
        for (int k = 0; k < 16; ++k) {
            float av[8], bv2[8];
            *(float4*)&av[0]  = *(const float4*)&As[k][ty * 8];
            *(float4*)&av[4]  = *(const float4*)&As[k][ty * 8 + 4];
            *(float4*)&bv2[0] = *(const float4*)&Bs[k][tx * 8];
            *(float4*)&bv2[4] = *(const float4*)&Bs[k][tx * 8 + 4];
#pragma unroll
            for (int i = 0; i < 8; ++i)
#pragma unroll
                for (int j = 0; j < 8; ++j)
                    acc[i][j] = fmaf(av[i], bv2[j], acc[i][j]);
        }
    }

    // epilogue
#pragma unroll
    for (int i = 0; i < 8; ++i) {
        const int co = bm0 + ty * 8 + i;
        const float bval = bias[co];
        float scale = 1.f, shift = bval;
        if (EPI == 1) {
            float s = bng[co] * rsqrtf(bnv[co] + 1e-5f);
            scale = s;
            shift = (bval - bnm[co]) * s + bnb[co];
        }
        float* yr = Y + ((size_t)b * Co + co) * N_SEQ + bn0 + tx * 8;
        const float* rr = (EPI == 2)
            ? (res + ((size_t)b * Co + co) * N_SEQ + bn0 + tx * 8) : nullptr;
#pragma unroll
        for (int jj = 0; jj < 8; jj += 4) {
            float4 o;
#pragma unroll
            for (int j2 = 0; j2 < 4; ++j2) {
                float v = acc[i][jj + j2];
                if (EPI == 1)      v = fmaxf(v * scale + shift, 0.f);
                else if (EPI == 2) v = v + bval + rr[jj + j2];
                else               v = v + bval;
                (&o.x)[j2] = v;
            }
            *(float4*)(yr + jj) = o;
        }
    }
}

// ---------------------------------------------------------------------------------------
// Flash attention, fp32. Layout: Q/K/V/O are (B, D, N) with channel c = dk*H + h (H=16).
// Block = one (b, h, 64-query tile). 256 threads as 16x16, 4x4 microtiles.
// smem: Qs[dk][n] (64x64), KPs = K tile [dk][m] aliased later with P[r][c] (64x64),
//       Vs[m][dk] stored with float4-granular XOR swizzle -> conflict-free both ways.
// Total smem = 48 KB exactly (static).
// ---------------------------------------------------------------------------------------
__global__ __launch_bounds__(256)
void attn_k(const float* __restrict__ Q, const float* __restrict__ K,
            const float* __restrict__ V, float* __restrict__ O)
{
    __shared__ float Qs[64 * 64];
    __shared__ float KPs[64 * 64];
    __shared__ float Vs[64 * 64];

    const int t  = threadIdx.x;
    const int tx = t & 15;
    const int ty = t >> 4;
    const int h  = blockIdx.y;
    const int b  = blockIdx.z;
    const int n0 = blockIdx.x * 64;

    const size_t base = ((size_t)b * D_MODEL + h) * N_SEQ;  // + dk*16*N + n
    const float* qb = Q + base;
    const float* kb = K + base;
    const float* vb = V + base;

    // load Q tile: Qs[dk][n]
    {
        const int n   = t & 63;
        const int dk0 = t >> 6;   // 0..3
#pragma unroll
        for (int p = 0; p < 16; ++p) {
            int dk = dk0 + p * 4;
            Qs[dk * 64 + n] = qb[(size_t)dk * 16 * N_SEQ + n0 + n];
        }
    }

    float o[4][4];
    float mrow[4], lrow[4];
#pragma unroll
    for (int i = 0; i < 4; ++i) {
        mrow[i] = -1e30f; lrow[i] = 0.f;
#pragma unroll
        for (int j = 0; j < 4; ++j) o[i][j] = 0.f;
    }

    for (int m0 = 0; m0 < N_SEQ; m0 += 64) {
        __syncthreads();   // previous tile's P/V reads complete
        // load K tile (Ks[dk][m]) and V tile (Vs[m][dk], XOR-swizzled float4 columns)
        {
            const int m   = t & 63;
            const int dk0 = t >> 6;
#pragma unroll
            for (int p = 0; p < 16; ++p) {
                int dk = dk0 + p * 4;
                size_t goff = (size_t)dk * 16 * N_SEQ + m0 + m;
                KPs[dk * 64 + m] = kb[goff];
                int c4 = (dk >> 2) ^ (m & 15);
                Vs[m * 64 + (c4 << 2) + (dk & 3)] = vb[goff];
            }
        }
        __syncthreads();

        // S = (Q^T K) / 8  — rows r = 4ty+i (queries), cols c = 4tx+j (keys)
        float s[4][4];
#pragma unroll
        for (int i = 0; i < 4; ++i)
#pragma unroll
            for (int j = 0; j < 4; ++j) s[i][j] = 0.f;

#pragma unroll 8
        for (int dk = 0; dk < 64; ++dk) {
            float4 a  = *(const float4*)&Qs[dk * 64 + 4 * ty];
            float4 bb = *(const float4*)&KPs[dk * 64 + 4 * tx];
            s[0][0] = fmaf(a.x, bb.x, s[0][0]); s[0][1] = fmaf(a.x, bb.y, s[0][1]);
            s[0][2] = fmaf(a.x, bb.z, s[0][2]); s[0][3] = fmaf(a.x, bb.w, s[0][3]);
            s[1][0] = fmaf(a.y, bb.x, s[1][0]); s[1][1] = fmaf(a.y, bb.y, s[1][1]);
            s[1][2] = fmaf(a.y, bb.z, s[1][2]); s[1][3] = fmaf(a.y, bb.w, s[1][3]);
            s[2][0] = fmaf(a.z, bb.x, s[2][0]); s[2][1] = fmaf(a.z, bb.y, s[2][1]);
            s[2][2] = fmaf(a.z, bb.z, s[2][2]); s[2][3] = fmaf(a.z, bb.w, s[2][3]);
            s[3][0] = fmaf(a.w, bb.x, s[3][0]); s[3][1] = fmaf(a.w, bb.y, s[3][1]);
            s[3][2] = fmaf(a.w, bb.z, s[3][2]); s[3][3] = fmaf(a.w, bb.w, s[3][3]);
        }

        // online softmax (row groups = 16 tx lanes sharing ty)
        float alpha[4];
#pragma unroll
        for (int i = 0; i < 4; ++i) {
#pragma unroll
            for (int j = 0; j < 4; ++j) s[i][j] *= 0.125f;
            float mx = fmaxf(fmaxf(s[i][0], s[i][1]), fmaxf(s[i][2], s[i][3]));
            mx = fmaxf(mx, __shfl_xor_sync(0xffffffffu, mx, 1));
            mx = fmaxf(mx, __shfl_xor_sync(0xffffffffu, mx, 2));
            mx = fmaxf(mx, __shfl_xor_sync(0xffffffffu, mx, 4));
            mx = fmaxf(mx, __shfl_xor_sync(0xffffffffu, mx, 8));
            float mn = fmaxf(mrow[i], mx);
            alpha[i] = __expf(mrow[i] - mn);
            mrow[i] = mn;
            float rs = 0.f;
#pragma unroll
            for (int j = 0; j < 4; ++j) { s[i][j] = __expf(s[i][j] - mn); rs += s[i][j]; }
            rs += __shfl_xor_sync(0xffffffffu, rs, 1);
            rs += __shfl_xor_sync(0xffffffffu, rs, 2);
            rs += __shfl_xor_sync(0xffffffffu, rs, 4);
            rs += __shfl_xor_sync(0xffffffffu, rs, 8);
            lrow[i] = lrow[i] * alpha[i] + rs;
#pragma unroll
            for (int j = 0; j < 4; ++j) o[i][j] *= alpha[i];
        }

        __syncthreads();   // everyone done reading K before P overwrites it
#pragma unroll
        for (int i = 0; i < 4; ++i)
            *(float4*)&KPs[(4 * ty + i) * 64 + 4 * tx] =
                make_float4(s[i][0], s[i][1], s[i][2], s[i][3]);
        __syncthreads();

        // O += P @ V   (o[r][d] += sum_c P[r][c] * V[c][d])
#pragma unroll 4
        for (int c = 0; c < 64; ++c) {
            float4 vv = *(const float4*)&Vs[c * 64 + ((tx ^ (c & 15)) << 2)];
            float p0 = KPs[(4 * ty + 0) * 64 + c];
            float p1 = KPs[(4 * ty + 1) * 64 + c];
            float p2 = KPs[(4 * ty + 2) * 64 + c];
            float p3 = KPs[(4 * ty + 3) * 64 + c];
            o[0][0] = fmaf(p0, vv.x, o[0][0]); o[0][1] = fmaf(p0, vv.y, o[0][1]);
            o[0][2] = fmaf(p0, vv.z, o[0][2]); o[0][3] = fmaf(p0, vv.w, o[0][3]);
            o[1][0] = fmaf(p1, vv.x, o[1][0]); o[1][1] = fmaf(p1, vv.y, o[1][1]);
            o[1][2] = fmaf(p1, vv.z, o[1][2]); o[1][3] = fmaf(p1, vv.w, o[1][3]);
            o[2][0] = fmaf(p2, vv.x, o[2][0]); o[2][1] = fmaf(p2, vv.y, o[2][1]);
            o[2][2] = fmaf(p2, vv.z, o[2][2]); o[2][3] = fmaf(p2, vv.w, o[2][3]);
            o[3][0] = fmaf(p3, vv.x, o[3][0]); o[3][1] = fmaf(p3, vv.y, o[3][1]);
            o[3][2] = fmaf(p3, vv.z, o[3][2]); o[3][3] = fmaf(p3, vv.w, o[3][3]);
        }
    }

    // normalize + write O[b, (4tx+j)*16 + h, n0 + 4ty + i]
#pragma unroll
    for (int i = 0; i < 4; ++i) {
        float inv = 1.f / lrow[i];
#pragma unroll
        for (int j = 0; j < 4; ++j) {
            int dk = 4 * tx + j;
            O[base + (size_t)dk * 16 * N_SEQ + (n0 + 4 * ty + i)] = o[i][j] * inv;
        }
    }
}

// ---------------------------------------------------------------------------------------
extern "C" void kernel_launch(void* const* d_in, const int* in_sizes, int n_in,
                              void* d_out, int out_size)
{
    (void)in_sizes; (void)n_in; (void)out_size;
    const float* motion = (const float*)d_in[0];
    const float* Wq  = (const float*)d_in[1];
    const float* bq  = (const float*)d_in[2];
    const float* Wk  = (const float*)d_in[3];
    const float* bk  = (const float*)d_in[4];
    const float* Wv  = (const float*)d_in[5];
    const float* bv  = (const float*)d_in[6];
    const float* Wm  = (const float*)d_in[7];
    const float* bm  = (const float*)d_in[8];
    const float* Wp1 = (const float*)d_in[9];
    const float* bp1 = (const float*)d_in[10];
    const float* bng = (const float*)d_in[11];
    const float* bnb = (const float*)d_in[12];
    const float* bnm = (const float*)d_in[13];
    const float* bnv = (const float*)d_in[14];
    const float* Wp2 = (const float*)d_in[15];
    const float* bp2 = (const float*)d_in[16];

    float *qb, *kb, *vb, *ab, *mb, *hb, *xb;
    cudaGetSymbolAddress((void**)&qb, g_q);
    cudaGetSymbolAddress((void**)&kb, g_k);
    cudaGetSymbolAddress((void**)&vb, g_v);
    cudaGetSymbolAddress((void**)&ab, g_a);
    cudaGetSymbolAddress((void**)&mb, g_m);
    cudaGetSymbolAddress((void**)&hb, g_h);
    cudaGetSymbolAddress((void**)&xb, g_x);

    dim3 blk(256);
    dim3 gP (N_SEQ / 128, D_MODEL / 128, B_BATCH);          // (8, 8, 4)
    dim3 gP1(N_SEQ / 128, (2 * D_MODEL) / 128, B_BATCH);    // (8, 16, 4)
    dim3 gA (N_SEQ / 64, H_HEADS, B_BATCH);                 // (16, 16, 4)

    for (int l = 0; l < 4; ++l) {
        const float* x   = (l == 0) ? motion : xb;
        float*       out = (l == 3) ? (float*)d_out : xb;
        const size_t wo  = (size_t)l * D_MODEL * D_MODEL;
        const size_t bo  = (size_t)l * D_MODEL;
        const size_t wo1 = (size_t)l * 4 * D_MODEL * D_MODEL;
        const size_t bo1 = (size_t)l * 2 * D_MODEL;
        const size_t wo2 = (size_t)l * 2 * D_MODEL * D_MODEL;

        gemm_k<0><<<gP, blk>>>(Wq + wo, bq + bo, x, D_MODEL, nullptr,
                               nullptr, nullptr, nullptr, nullptr, nullptr,
                               qb, D_MODEL, D_MODEL);
        gemm_k<0><<<gP, blk>>>(Wk + wo, bk + bo, x, D_MODEL, nullptr,
                               nullptr, nullptr, nullptr, nullptr, nullptr,
                               kb, D_MODEL, D_MODEL);
        gemm_k<0><<<gP, blk>>>(Wv + wo, bv + bo, x, D_MODEL, nullptr,
                               nullptr, nullptr, nullptr, nullptr, nullptr,
                               vb, D_MODEL, D_MODEL);
        attn_k<<<gA, blk>>>(qb, kb, vb, ab);
        gemm_k<0><<<gP, blk>>>(Wm + wo, bm + bo, ab, D_MODEL, nullptr,
                               nullptr, nullptr, nullptr, nullptr, nullptr,
                               mb, D_MODEL, D_MODEL);
        // p1: input = concat([merged, x]) read in-place; epilogue = BN(eval) + ReLU
        gemm_k<1><<<gP1, blk>>>(Wp1 + wo1, bp1 + bo1, mb, D_MODEL, x,
                                bng + bo1, bnb + bo1, bnm + bo1, bnv + bo1, nullptr,
                                hb, 2 * D_MODEL, 2 * D_MODEL);
        // p2: epilogue = + residual x; last layer writes d_out directly
        gemm_k<2><<<gP, blk>>>(Wp2 + wo2, bp2 + bo, hb, 2 * D_MODEL, nullptr,
                               nullptr, nullptr, nullptr, nullptr, x,
                               out, D_MODEL, 2 * D_MODEL);
    }
}

// round 2
// speedup vs baseline: 1.2861x; 1.2861x over previous
#include <cuda_runtime.h>
#include <cstdint>

#define D_MODEL 1024
#define N_SEQ   1024
#define B_BATCH 4
#define H_HEADS 16
// DK = 64

// ---------------- scratch (static device globals; no runtime allocation) ----------------
__device__ float g_q[(size_t)B_BATCH * D_MODEL * N_SEQ];
__device__ float g_k[(size_t)B_BATCH * D_MODEL * N_SEQ];
__device__ float g_v[(size_t)B_BATCH * D_MODEL * N_SEQ];
__device__ float g_a[(size_t)B_BATCH * D_MODEL * N_SEQ];
__device__ float g_m[(size_t)B_BATCH * D_MODEL * N_SEQ];
__device__ float g_h[(size_t)B_BATCH * 2 * D_MODEL * N_SEQ];
__device__ float g_x[(size_t)B_BATCH * D_MODEL * N_SEQ];

// ---------------------------------------------------------------------------------------
// TF32 helpers
// ---------------------------------------------------------------------------------------
__device__ __forceinline__ uint32_t f2tf32(float x) {
    uint32_t r;
    asm("cvt.rna.tf32.f32 %0, %1;" : "=r"(r) : "f"(x));
    return r;
}

__device__ __forceinline__ void mma_tf32(float& c0, float& c1, float& c2, float& c3,
                                         uint32_t a0, uint32_t a1, uint32_t a2, uint32_t a3,
                                         uint32_t b0, uint32_t b1) {
    asm volatile(
        "mma.sync.aligned.m16n8k8.row.col.f32.tf32.tf32.f32 "
        "{%0,%1,%2,%3}, {%4,%5,%6,%7}, {%8,%9}, {%0,%1,%2,%3};"
        : "+f"(c0), "+f"(c1), "+f"(c2), "+f"(c3)
        : "r"(a0), "r"(a1), "r"(a2), "r"(a3), "r"(b0), "r"(b1));
}

// ---------------------------------------------------------------------------------------
// TF32 tensor-core batched GEMM:  Y[b] = W (Co x Ci) @ X[b] (Ci x N) + bias, epilogues:
//   EPI 0: Y = WX + bias
//   EPI 1: Y = relu( bn_g * (WX + bias - bn_mu) * rsqrt(bn_var+eps) + bn_b )
//   EPI 2: Y = WX + bias + res
// Input X is logically the concat of X0 (rows0 channels) then X1 (Ci-rows0 channels).
// 128x128 C tile, 256 threads = 8 warps (2m x 4n), warp = 64x32 via 4x4 m16n8k8 tiles.
// K-step 16, double-buffered smem in FRAGMENT-MAJOR layout:
//   A frag (16x8): elem(r,c): lane=(r%8)*4+(c%4), reg=(r>=8)+2*(c>=4) -> one LDS.128
//   B frag (8x8):  elem(k,n): lane=(n%8)*4+(k%4), reg=(k>=4)          -> one LDS.64
// tf32 conversion happens at staging time.
// ---------------------------------------------------------------------------------------
template<int EPI>
__global__ __launch_bounds__(256, 2)
void gemm_tc(const float* __restrict__ W, const float* __restrict__ bias,
             const float* __restrict__ X0, int rows0,
             const float* __restrict__ X1,
             const float* __restrict__ bng, const float* __restrict__ bnb,
             const float* __restrict__ bnm, const float* __restrict__ bnv,
             const float* __restrict__ res,
             float* __restrict__ Y, int Co, int Ci)
{
    __shared__ __align__(16) uint32_t As[2][2048];  // [buf][(kk*8+mi)*128 + lane*4 + reg]
    __shared__ __align__(16) uint32_t Bs[2][2048];  // [buf][((kk*16+ni)*32 + lane)*2 + reg]

    const int t    = threadIdx.x;
    const int lane = t & 31;
    const int warp = t >> 5;
    const int wm   = warp & 1;   // 0..1 -> 64 rows
    const int wn   = warp >> 1;  // 0..3 -> 32 cols
    const int b    = blockIdx.z;
    const int bm0  = blockIdx.y * 128;
    const int bn0  = blockIdx.x * 128;

    // ---- A staging: thread -> (row = t>>1, kk = t&1), 2x float4 per k16-step
    const int a_r   = t >> 1;
    const int a_kk  = t & 1;
    const int a_mi  = a_r >> 4;
    const int a_rl  = a_r & 15;
    const int a_lb  = (a_rl & 7) * 4;   // lane base
    const int a_rh  = a_rl >> 3;        // reg bit0
    const float* wptr = W + (size_t)(bm0 + a_r) * Ci + a_kk * 8;
    uint32_t* a_dst_base = &As[0][0] + (a_kk * 8 + a_mi) * 128 + a_lb * 4 + a_rh;

    // ---- B staging: thread -> (k = t>>4, n8 = (t&15)*8), 2x float4 per step
    const int b_k   = t >> 4;           // 0..15
    const int b_ni  = t & 15;           // n/8
    const int b_kk  = b_k >> 3;
    const int b_kl  = b_k & 7;
    const int b_t2  = b_kl & 3;
    const int b_rg  = b_kl >> 2;
    const int rows1 = Ci - rows0;
    uint32_t* b_dst_base = &Bs[0][0] + ((b_kk * 16 + b_ni) * 32 + b_t2) * 2 + b_rg;

    float acc[4][4][4];
#pragma unroll
    for (int mi = 0; mi < 4; ++mi)
#pragma unroll
        for (int ni = 0; ni < 4; ++ni)
#pragma unroll
            for (int r = 0; r < 4; ++r) acc[mi][ni][r] = 0.f;

    float4 ra[2], rb[2];

    // prologue global loads (kt = 0)
    {
        ra[0] = *(const float4*)(wptr);
        ra[1] = *(const float4*)(wptr + 4);
        int ci = b_k;
        const float* src = (ci < rows0)
            ? (X0 + ((size_t)b * rows0 + ci) * N_SEQ)
            : (X1 + ((size_t)b * rows1 + (ci - rows0)) * N_SEQ);
        rb[0] = *(const float4*)(src + bn0 + b_ni * 8);
        rb[1] = *(const float4*)(src + bn0 + b_ni * 8 + 4);
    }

    int buf = 0;
    for (int kt = 0; kt < Ci; kt += 16) {
        // stage (with tf32 conversion)
        {
            uint32_t* ad = a_dst_base + buf * 2048;
#pragma unroll
            for (int q = 0; q < 2; ++q) {
                uint32_t* d = ad + 2 * q;
                d[0]  = f2tf32(ra[q].x);
                d[4]  = f2tf32(ra[q].y);
                d[8]  = f2tf32(ra[q].z);
                d[12] = f2tf32(ra[q].w);
            }
            uint32_t* bd = b_dst_base + buf * 2048;
#pragma unroll
            for (int q = 0; q < 2; ++q) {
                uint32_t* d = bd + 32 * q;   // g advances by 4 -> lane +16 -> addr +32
                d[0]  = f2tf32(rb[q].x);
                d[8]  = f2tf32(rb[q].y);
                d[16] = f2tf32(rb[q].z);
                d[24] = f2tf32(rb[q].w);
            }
        }
        __syncthreads();

        // prefetch next k16 tile into registers
        if (kt + 16 < Ci) {
            ra[0] = *(const float4*)(wptr + kt + 16);
            ra[1] = *(const float4*)(wptr + kt + 16 + 4);
            int ci = kt + 16 + b_k;
            const float* src = (ci < rows0)
                ? (X0 + ((size_t)b * rows0 + ci) * N_SEQ)
                : (X1 + ((size_t)b * rows1 + (ci - rows0)) * N_SEQ);
            rb[0] = *(const float4*)(src + bn0 + b_ni * 8);
            rb[1] = *(const float4*)(src + bn0 + b_ni * 8 + 4);
        }

        // compute: 2 kk-steps of m16n8k8
        const uint4* As4 = reinterpret_cast<const uint4*>(&As[buf][0]);
        const uint2* Bs2 = reinterpret_cast<const uint2*>(&Bs[buf][0]);
#pragma unroll
        for (int kk = 0; kk < 2; ++kk) {
            uint4 af[4];
            uint2 bf[4];
#pragma unroll
            for (int mi = 0; mi < 4; ++mi)
                af[mi] = As4[(kk * 8 + wm * 4 + mi) * 32 + lane];
#pragma unroll
            for (int ni = 0; ni < 4; ++ni)
                bf[ni] = Bs2[(kk * 16 + wn * 4 + ni) * 32 + lane];
#pragma unroll
            for (int mi = 0; mi < 4; ++mi)
#pragma unroll
                for (int ni = 0; ni < 4; ++ni)
                    mma_tf32(acc[mi][ni][0], acc[mi][ni][1], acc[mi][ni][2], acc[mi][ni][3],
                             af[mi].x, af[mi].y, af[mi].z, af[mi].w,
                             bf[ni].x, bf[ni].y);
        }
        buf ^= 1;
    }

    // ---- epilogue ----
    const int g  = lane >> 2;
    const int tt = lane & 3;
#pragma unroll
    for (int mi = 0; mi < 4; ++mi) {
        const int r0 = bm0 + wm * 64 + mi * 16 + g;
        const int r1 = r0 + 8;
        float sc0 = 1.f, sh0, sc1 = 1.f, sh1;
        {
            float bv0 = bias[r0], bv1 = bias[r1];
            if (EPI == 1) {
                float s0 = bng[r0] * rsqrtf(bnv[r0] + 1e-5f);
                float s1 = bng[r1] * rsqrtf(bnv[r1] + 1e-5f);
                sc0 = s0; sh0 = (bv0 - bnm[r0]) * s0 + bnb[r0];
                sc1 = s1; sh1 = (bv1 - bnm[r1]) * s1 + bnb[r1];
            } else {
                sh0 = bv0; sh1 = bv1;
            }
        }
        float* y0 = Y + ((size_t)b * Co + r0) * N_SEQ;
        float* y1 = Y + ((size_t)b * Co + r1) * N_SEQ;
        const float* rr0 = (EPI == 2) ? (res + ((size_t)b * Co + r0) * N_SEQ) : nullptr;
        const float* rr1 = (EPI == 2) ? (res + ((size_t)b * Co + r1) * N_SEQ) : nullptr;
#pragma unroll
        for (int ni = 0; ni < 4; ++ni) {
            const int col = bn0 + wn * 32 + ni * 8 + 2 * tt;
            float v0 = acc[mi][ni][0], v1 = acc[mi][ni][1];
            float v2 = acc[mi][ni][2], v3 = acc[mi][ni][3];
            if (EPI == 1) {
                v0 = fmaxf(v0 * sc0 + sh0, 0.f);
                v1 = fmaxf(v1 * sc0 + sh0, 0.f);
                v2 = fmaxf(v2 * sc1 + sh1, 0.f);
                v3 = fmaxf(v3 * sc1 + sh1, 0.f);
            } else if (EPI == 2) {
                float2 q0 = *(const float2*)(rr0 + col);
                float2 q1 = *(const float2*)(rr1 + col);
                v0 += sh0 + q0.x; v1 += sh0 + q0.y;
                v2 += sh1 + q1.x; v3 += sh1 + q1.y;
            } else {
                v0 += sh0; v1 += sh0; v2 += sh1; v3 += sh1;
            }
            *(float2*)(y0 + col) = make_float2(v0, v1);
            *(float2*)(y1 + col) = make_float2(v2, v3);
        }
    }
}

// ---------------------------------------------------------------------------------------
// Flash attention, fp32 (unchanged from R1). Layout: (B, D, N), channel c = dk*H + h.
// ---------------------------------------------------------------------------------------
__global__ __launch_bounds__(256)
void attn_k(const float* __restrict__ Q, const float* __restrict__ K,
            const float* __restrict__ V, float* __restrict__ O)
{
    __shared__ float Qs[64 * 64];
    __shared__ float KPs[64 * 64];
    __shared__ float Vs[64 * 64];

    const int t  = threadIdx.x;
    const int tx = t & 15;
    const int ty = t >> 4;
    const int h  = blockIdx.y;
    const int b  = blockIdx.z;
    const int n0 = blockIdx.x * 64;

    const size_t base = ((size_t)b * D_MODEL + h) * N_SEQ;
    const float* qb = Q + base;
    const float* kb = K + base;
    const float* vb = V + base;

    {
        const int n   = t & 63;
        const int dk0 = t >> 6;
#pragma unroll
        for (int p = 0; p < 16; ++p) {
            int dk = dk0 + p * 4;
            Qs[dk * 64 + n] = qb[(size_t)dk * 16 * N_SEQ + n0 + n];
        }
    }

    float o[4][4];
    float mrow[4], lrow[4];
#pragma unroll
    for (int i = 0; i < 4; ++i) {
        mrow[i] = -1e30f; lrow[i] = 0.f;
#pragma unroll
        for (int j = 0; j < 4; ++j) o[i][j] = 0.f;
    }

    for (int m0 = 0; m0 < N_SEQ; m0 += 64) {
        __syncthreads();
        {
            const int m   = t & 63;
            const int dk0 = t >> 6;
#pragma unroll
            for (int p = 0; p < 16; ++p) {
                int dk = dk0 + p * 4;
                size_t goff = (size_t)dk * 16 * N_SEQ + m0 + m;
                KPs[dk * 64 + m] = kb[goff];
                int c4 = (dk >> 2) ^ (m & 15);
                Vs[m * 64 + (c4 << 2) + (dk & 3)] = vb[goff];
            }
        }
        __syncthreads();

        float s[4][4];
#pragma unroll
        for (int i = 0; i < 4; ++i)
#pragma unroll
            for (int j = 0; j < 4; ++j) s[i][j] = 0.f;

#pragma unroll 8
        for (int dk = 0; dk < 64; ++dk) {
            float4 a  = *(const float4*)&Qs[dk * 64 + 4 * ty];
            float4 bb = *(const float4*)&KPs[dk * 64 + 4 * tx];
            s[0][0] = fmaf(a.x, bb.x, s[0][0]); s[0][1] = fmaf(a.x, bb.y, s[0][1]);
            s[0][2] = fmaf(a.x, bb.z, s[0][2]); s[0][3] = fmaf(a.x, bb.w, s[0][3]);
            s[1][0] = fmaf(a.y, bb.x, s[1][0]); s[1][1] = fmaf(a.y, bb.y, s[1][1]);
            s[1][2] = fmaf(a.y, bb.z, s[1][2]); s[1][3] = fmaf(a.y, bb.w, s[1][3]);
            s[2][0] = fmaf(a.z, bb.x, s[2][0]); s[2][1] = fmaf(a.z, bb.y, s[2][1]);
            s[2][2] = fmaf(a.z, bb.z, s[2][2]); s[2][3] = fmaf(a.z, bb.w, s[2][3]);
            s[3][0] = fmaf(a.w, bb.x, s[3][0]); s[3][1] = fmaf(a.w, bb.y, s[3][1]);
            s[3][2] = fmaf(a.w, bb.z, s[3][2]); s[3][3] = fmaf(a.w, bb.w, s[3][3]);
        }

        float alpha[4];
#pragma unroll
        for (int i = 0; i < 4; ++i) {
#pragma unroll
            for (int j = 0; j < 4; ++j) s[i][j] *= 0.125f;
            float mx = fmaxf(fmaxf(s[i][0], s[i][1]), fmaxf(s[i][2], s[i][3]));
            mx = fmaxf(mx, __shfl_xor_sync(0xffffffffu, mx, 1));
            mx = fmaxf(mx, __shfl_xor_sync(0xffffffffu, mx, 2));
            mx = fmaxf(mx, __shfl_xor_sync(0xffffffffu, mx, 4));
            mx = fmaxf(mx, __shfl_xor_sync(0xffffffffu, mx, 8));
            float mn = fmaxf(mrow[i], mx);
            alpha[i] = __expf(mrow[i] - mn);
            mrow[i] = mn;
            float rs = 0.f;
#pragma unroll
            for (int j = 0; j < 4; ++j) { s[i][j] = __expf(s[i][j] - mn); rs += s[i][j]; }
            rs += __shfl_xor_sync(0xffffffffu, rs, 1);
            rs += __shfl_xor_sync(0xffffffffu, rs, 2);
            rs += __shfl_xor_sync(0xffffffffu, rs, 4);
            rs += __shfl_xor_sync(0xffffffffu, rs, 8);
            lrow[i] = lrow[i] * alpha[i] + rs;
#pragma unroll
            for (int j = 0; j < 4; ++j) o[i][j] *= alpha[i];
        }

        __syncthreads();
#pragma unroll
        for (int i = 0; i < 4; ++i)
            *(float4*)&KPs[(4 * ty + i) * 64 + 4 * tx] =
                make_float4(s[i][0], s[i][1], s[i][2], s[i][3]);
        __syncthreads();

#pragma unroll 4
        for (int c = 0; c < 64; ++c) {
            float4 vv = *(const float4*)&Vs[c * 64 + ((tx ^ (c & 15)) << 2)];
            float p0 = KPs[(4 * ty + 0) * 64 + c];
            float p1 = KPs[(4 * ty + 1) * 64 + c];
            float p2 = KPs[(4 * ty + 2) * 64 + c];
            float p3 = KPs[(4 * ty + 3) * 64 + c];
            o[0][0] = fmaf(p0, vv.x, o[0][0]); o[0][1] = fmaf(p0, vv.y, o[0][1]);
            o[0][2] = fmaf(p0, vv.z, o[0][2]); o[0][3] = fmaf(p0, vv.w, o[0][3]);
            o[1][0] = fmaf(p1, vv.x, o[1][0]); o[1][1] = fmaf(p1, vv.y, o[1][1]);
            o[1][2] = fmaf(p1, vv.z, o[1][2]); o[1][3] = fmaf(p1, vv.w, o[1][3]);
            o[2][0] = fmaf(p2, vv.x, o[2][0]); o[2][1] = fmaf(p2, vv.y, o[2][1]);
            o[2][2] = fmaf(p2, vv.z, o[2][2]); o[2][3] = fmaf(p2, vv.w, o[2][3]);
            o[3][0] = fmaf(p3, vv.x, o[3][0]); o[3][1] = fmaf(p3, vv.y, o[3][1]);
            o[3][2] = fmaf(p3, vv.z, o[3][2]); o[3][3] = fmaf(p3, vv.w, o[3][3]);
        }
    }

#pragma unroll
    for (int i = 0; i < 4; ++i) {
        float inv = 1.f / lrow[i];
#pragma unroll
        for (int j = 0; j < 4; ++j) {
            int dk = 4 * tx + j;
            O[base + (size_t)dk * 16 * N_SEQ + (n0 + 4 * ty + i)] = o[i][j] * inv;
        }
    }
}

// ---------------------------------------------------------------------------------------
extern "C" void kernel_launch(void* const* d_in, const int* in_sizes, int n_in,
                              void* d_out, int out_size)
{
    (void)in_sizes; (void)n_in; (void)out_size;
    const float* motion = (const float*)d_in[0];
    const float* Wq  = (const float*)d_in[1];
    const float* bq  = (const float*)d_in[2];
    const float* Wk  = (const float*)d_in[3];
    const float* bk  = (const float*)d_in[4];
    const float* Wv  = (const float*)d_in[5];
    const float* bv  = (const float*)d_in[6];
    const float* Wm  = (const float*)d_in[7];
    const float* bm  = (const float*)d_in[8];
    const float* Wp1 = (const float*)d_in[9];
    const float* bp1 = (const float*)d_in[10];
    const float* bng = (const float*)d_in[11];
    const float* bnb = (const float*)d_in[12];
    const float* bnm = (const float*)d_in[13];
    const float* bnv = (const float*)d_in[14];
    const float* Wp2 = (const float*)d_in[15];
    const float* bp2 = (const float*)d_in[16];

    float *qb, *kb, *vb, *ab, *mb, *hb, *xb;
    cudaGetSymbolAddress((void**)&qb, g_q);
    cudaGetSymbolAddress((void**)&kb, g_k);
    cudaGetSymbolAddress((void**)&vb, g_v);
    cudaGetSymbolAddress((void**)&ab, g_a);
    cudaGetSymbolAddress((void**)&mb, g_m);
    cudaGetSymbolAddress((void**)&hb, g_h);
    cudaGetSymbolAddress((void**)&xb, g_x);

    dim3 blk(256);
    dim3 gP (N_SEQ / 128, D_MODEL / 128, B_BATCH);          // (8, 8, 4)
    dim3 gP1(N_SEQ / 128, (2 * D_MODEL) / 128, B_BATCH);    // (8, 16, 4)
    dim3 gA (N_SEQ / 64, H_HEADS, B_BATCH);                 // (16, 16, 4)

    for (int l = 0; l < 4; ++l) {
        const float* x   = (l == 0) ? motion : xb;
        float*       out = (l == 3) ? (float*)d_out : xb;
        const size_t wo  = (size_t)l * D_MODEL * D_MODEL;
        const size_t bo  = (size_t)l * D_MODEL;
        const size_t wo1 = (size_t)l * 4 * D_MODEL * D_MODEL;
        const size_t bo1 = (size_t)l * 2 * D_MODEL;
        const size_t wo2 = (size_t)l * 2 * D_MODEL * D_MODEL;

        gemm_tc<0><<<gP, blk>>>(Wq + wo, bq + bo, x, D_MODEL, nullptr,
                                nullptr, nullptr, nullptr, nullptr, nullptr,
                                qb, D_MODEL, D_MODEL);
        gemm_tc<0><<<gP, blk>>>(Wk + wo, bk + bo, x, D_MODEL, nullptr,
                                nullptr, nullptr, nullptr, nullptr, nullptr,
                                kb, D_MODEL, D_MODEL);
        gemm_tc<0><<<gP, blk>>>(Wv + wo, bv + bo, x, D_MODEL, nullptr,
                                nullptr, nullptr, nullptr, nullptr, nullptr,
                                vb, D_MODEL, D_MODEL);
        attn_k<<<gA, blk>>>(qb, kb, vb, ab);
        gemm_tc<0><<<gP, blk>>>(Wm + wo, bm + bo, ab, D_MODEL, nullptr,
                                nullptr, nullptr, nullptr, nullptr, nullptr,
                                mb, D_MODEL, D_MODEL);
        // p1: input = concat([merged, x]) read in-place; epilogue = BN(eval) + ReLU
        gemm_tc<1><<<gP1, blk>>>(Wp1 + wo1, bp1 + bo1, mb, D_MODEL, x,
                                 bng + bo1, bnb + bo1, bnm + bo1, bnv + bo1, nullptr,
                                 hb, 2 * D_MODEL, 2 * D_MODEL);
        // p2: epilogue = + residual x; last layer writes d_out directly
        gemm_tc<2><<<gP, blk>>>(Wp2 + wo2, bp2 + bo, hb, 2 * D_MODEL, nullptr,
                                nullptr, nullptr, nullptr, nullptr, x,
                                out, D_MODEL, 2 * D_MODEL);
    }
}

// round 3
// speedup vs baseline: 2.0209x; 1.5713x over previous
#include <cuda_runtime.h>
#include <cstdint>

#define D_MODEL 1024
#define N_SEQ   1024
#define B_BATCH 4
#define H_HEADS 16
// DK = 64

// ---------------- scratch (static device globals; no runtime allocation) ----------------
__device__ float g_q[(size_t)B_BATCH * D_MODEL * N_SEQ];
__device__ float g_k[(size_t)B_BATCH * D_MODEL * N_SEQ];
__device__ float g_v[(size_t)B_BATCH * D_MODEL * N_SEQ];
__device__ float g_a[(size_t)B_BATCH * D_MODEL * N_SEQ];
__device__ float g_m[(size_t)B_BATCH * D_MODEL * N_SEQ];
__device__ float g_h[(size_t)B_BATCH * 2 * D_MODEL * N_SEQ];
__device__ float g_x[(size_t)B_BATCH * D_MODEL * N_SEQ];

// ---------------------------------------------------------------------------------------
// TF32 helpers
// ---------------------------------------------------------------------------------------
__device__ __forceinline__ uint32_t f2tf32(float x) {
    uint32_t r;
    asm("cvt.rna.tf32.f32 %0, %1;" : "=r"(r) : "f"(x));
    return r;
}

__device__ __forceinline__ void mma_tf32(float& c0, float& c1, float& c2, float& c3,
                                         uint32_t a0, uint32_t a1, uint32_t a2, uint32_t a3,
                                         uint32_t b0, uint32_t b1) {
    asm volatile(
        "mma.sync.aligned.m16n8k8.row.col.f32.tf32.tf32.f32 "
        "{%0,%1,%2,%3}, {%4,%5,%6,%7}, {%8,%9}, {%0,%1,%2,%3};"
        : "+f"(c0), "+f"(c1), "+f"(c2), "+f"(c3)
        : "r"(a0), "r"(a1), "r"(a2), "r"(a3), "r"(b0), "r"(b1));
}

// ---------------------------------------------------------------------------------------
// TF32 tensor-core batched GEMM:  Y[b] = W (Co x Ci) @ X[b] (Ci x N) + bias, epilogues:
//   EPI 0: Y = WX + bias
//   EPI 1: Y = relu( bn_g * (WX + bias - bn_mu) * rsqrt(bn_var+eps) + bn_b )
//   EPI 2: Y = WX + bias + res
// Input X is logically the concat of X0 (rows0 channels) then X1 (Ci-rows0 channels).
// 128x128 C tile, 256 threads = 8 warps (2m x 4n), warp = 64x32 via 4x4 m16n8k8 tiles.
// K-step 16, double-buffered canonical k-major smem:
//   As[k][m], Bs[k][n], row stride 136 words (128 + 8 pad).
//   Fragment reads: lane l -> (k=l%4, mn=l/4): bank = 8*(l%4)+(l/4) -> bijection on 32
//   banks -> CONFLICT-FREE. Stores: A column st.32 2-way, B row st.v4 2-way.
// tf32 conversion happens at staging time.
// ---------------------------------------------------------------------------------------
#define SROW 136

template<int EPI>
__global__ __launch_bounds__(256, 2)
void gemm_tc(const float* __restrict__ W, const float* __restrict__ bias,
             const float* __restrict__ X0, int rows0,
             const float* __restrict__ X1,
             const float* __restrict__ bng, const float* __restrict__ bnb,
             const float* __restrict__ bnm, const float* __restrict__ bnv,
             const float* __restrict__ res,
             float* __restrict__ Y, int Co, int Ci)
{
    __shared__ __align__(16) uint32_t As[2][16 * SROW];
    __shared__ __align__(16) uint32_t Bs[2][16 * SROW];

    const int t    = threadIdx.x;
    const int lane = t & 31;
    const int warp = t >> 5;
    const int wm   = warp & 1;   // 0..1 -> 64 rows
    const int wn   = warp >> 1;  // 0..3 -> 32 cols
    const int l4   = lane & 3;
    const int lg   = lane >> 2;
    const int b    = blockIdx.z;
    const int bm0  = blockIdx.y * 128;
    const int bn0  = blockIdx.x * 128;

    // ---- A staging: thread -> (row a_r = t>>1, kk = t&1), 8 floats of W row
    const int a_r  = t >> 1;
    const int a_kk = t & 1;
    const float* wptr = W + (size_t)(bm0 + a_r) * Ci + a_kk * 8;

    // ---- B staging: thread -> (k = t>>4, n8 = (t&15)*8)
    const int b_k   = t >> 4;           // 0..15
    const int b_ni  = t & 15;           // n/8
    const int rows1 = Ci - rows0;

    float acc[4][4][4];
#pragma unroll
    for (int mi = 0; mi < 4; ++mi)
#pragma unroll
        for (int ni = 0; ni < 4; ++ni)
#pragma unroll
            for (int r = 0; r < 4; ++r) acc[mi][ni][r] = 0.f;

    float4 ra[2], rb[2];

    // prologue global loads (kt = 0)
    {
        ra[0] = *(const float4*)(wptr);
        ra[1] = *(const float4*)(wptr + 4);
        int ci = b_k;
        const float* src = (ci < rows0)
            ? (X0 + ((size_t)b * rows0 + ci) * N_SEQ)
            : (X1 + ((size_t)b * rows1 + (ci - rows0)) * N_SEQ);
        rb[0] = *(const float4*)(src + bn0 + b_ni * 8);
        rb[1] = *(const float4*)(src + bn0 + b_ni * 8 + 4);
    }

    int buf = 0;
    for (int kt = 0; kt < Ci; kt += 16) {
        // ---- stage with tf32 conversion ----
        {
            // A: column writes As[kk*8+i][a_r]
            uint32_t* ad = &As[buf][0] + (a_kk * 8) * SROW + a_r;
            ad[0 * SROW] = f2tf32(ra[0].x);
            ad[1 * SROW] = f2tf32(ra[0].y);
            ad[2 * SROW] = f2tf32(ra[0].z);
            ad[3 * SROW] = f2tf32(ra[0].w);
            ad[4 * SROW] = f2tf32(ra[1].x);
            ad[5 * SROW] = f2tf32(ra[1].y);
            ad[6 * SROW] = f2tf32(ra[1].z);
            ad[7 * SROW] = f2tf32(ra[1].w);
            // B: row writes Bs[b_k][8*ni .. +7], two st.v4
            uint32_t* bd = &Bs[buf][0] + b_k * SROW + b_ni * 8;
            uint4 p0, p1;
            p0.x = f2tf32(rb[0].x); p0.y = f2tf32(rb[0].y);
            p0.z = f2tf32(rb[0].z); p0.w = f2tf32(rb[0].w);
            p1.x = f2tf32(rb[1].x); p1.y = f2tf32(rb[1].y);
            p1.z = f2tf32(rb[1].z); p1.w = f2tf32(rb[1].w);
            *(uint4*)(bd)     = p0;
            *(uint4*)(bd + 4) = p1;
        }
        __syncthreads();

        // prefetch next k16 tile into registers
        if (kt + 16 < Ci) {
            ra[0] = *(const float4*)(wptr + kt + 16);
            ra[1] = *(const float4*)(wptr + kt + 16 + 4);
            int ci = kt + 16 + b_k;
            const float* src = (ci < rows0)
                ? (X0 + ((size_t)b * rows0 + ci) * N_SEQ)
                : (X1 + ((size_t)b * rows1 + (ci - rows0)) * N_SEQ);
            rb[0] = *(const float4*)(src + bn0 + b_ni * 8);
            rb[1] = *(const float4*)(src + bn0 + b_ni * 8 + 4);
        }

        // ---- compute: 2 kk-steps of m16n8k8 ----
        const uint32_t* Ab = &As[buf][0];
        const uint32_t* Bb = &Bs[buf][0];
#pragma unroll
        for (int kk = 0; kk < 2; ++kk) {
            const int a_off = (kk * 8 + l4) * SROW + wm * 64 + lg;
            const int b_off = (kk * 8 + l4) * SROW + wn * 32 + lg;
            uint32_t af[4][4];
            uint32_t bf[4][2];
#pragma unroll
            for (int mi = 0; mi < 4; ++mi) {
                af[mi][0] = Ab[a_off + mi * 16];
                af[mi][1] = Ab[a_off + mi * 16 + 8];
                af[mi][2] = Ab[a_off + mi * 16 + 4 * SROW];
                af[mi][3] = Ab[a_off + mi * 16 + 4 * SROW + 8];
            }
#pragma unroll
            for (int ni = 0; ni < 4; ++ni) {
                bf[ni][0] = Bb[b_off + ni * 8];
                bf[ni][1] = Bb[b_off + ni * 8 + 4 * SROW];
            }
#pragma unroll
            for (int mi = 0; mi < 4; ++mi)
#pragma unroll
                for (int ni = 0; ni < 4; ++ni)
                    mma_tf32(acc[mi][ni][0], acc[mi][ni][1], acc[mi][ni][2], acc[mi][ni][3],
                             af[mi][0], af[mi][1], af[mi][2], af[mi][3],
                             bf[ni][0], bf[ni][1]);
        }
        buf ^= 1;
    }

    // ---- epilogue ----
    const int g  = lane >> 2;
    const int tt = lane & 3;
#pragma unroll
    for (int mi = 0; mi < 4; ++mi) {
        const int r0 = bm0 + wm * 64 + mi * 16 + g;
        const int r1 = r0 + 8;
        float sc0 = 1.f, sh0, sc1 = 1.f, sh1;
        {
            float bv0 = bias[r0], bv1 = bias[r1];
            if (EPI == 1) {
                float s0 = bng[r0] * rsqrtf(bnv[r0] + 1e-5f);
                float s1 = bng[r1] * rsqrtf(bnv[r1] + 1e-5f);
                sc0 = s0; sh0 = (bv0 - bnm[r0]) * s0 + bnb[r0];
                sc1 = s1; sh1 = (bv1 - bnm[r1]) * s1 + bnb[r1];
            } else {
                sh0 = bv0; sh1 = bv1;
            }
        }
        float* y0 = Y + ((size_t)b * Co + r0) * N_SEQ;
        float* y1 = Y + ((size_t)b * Co + r1) * N_SEQ;
        const float* rr0 = (EPI == 2) ? (res + ((size_t)b * Co + r0) * N_SEQ) : nullptr;
        const float* rr1 = (EPI == 2) ? (res + ((size_t)b * Co + r1) * N_SEQ) : nullptr;
#pragma unroll
        for (int ni = 0; ni < 4; ++ni) {
            const int col = bn0 + wn * 32 + ni * 8 + 2 * tt;
            float v0 = acc[mi][ni][0], v1 = acc[mi][ni][1];
            float v2 = acc[mi][ni][2], v3 = acc[mi][ni][3];
            if (EPI == 1) {
                v0 = fmaxf(v0 * sc0 + sh0, 0.f);
                v1 = fmaxf(v1 * sc0 + sh0, 0.f);
                v2 = fmaxf(v2 * sc1 + sh1, 0.f);
                v3 = fmaxf(v3 * sc1 + sh1, 0.f);
            } else if (EPI == 2) {
                float2 q0 = *(const float2*)(rr0 + col);
                float2 q1 = *(const float2*)(rr1 + col);
                v0 += sh0 + q0.x; v1 += sh0 + q0.y;
                v2 += sh1 + q1.x; v3 += sh1 + q1.y;
            } else {
                v0 += sh0; v1 += sh0; v2 += sh1; v3 += sh1;
            }
            *(float2*)(y0 + col) = make_float2(v0, v1);
            *(float2*)(y1 + col) = make_float2(v2, v3);
        }
    }
}

// ---------------------------------------------------------------------------------------
// Flash attention, fp32 (unchanged). Layout: (B, D, N), channel c = dk*H + h.
// ---------------------------------------------------------------------------------------
__global__ __launch_bounds__(256)
void attn_k(const float* __restrict__ Q, const float* __restrict__ K,
            const float* __restrict__ V, float* __restrict__ O)
{
    __shared__ float Qs[64 * 64];
    __shared__ float KPs[64 * 64];
    __shared__ float Vs[64 * 64];

    const int t  = threadIdx.x;
    const int tx = t & 15;
    const int ty = t >> 4;
    const int h  = blockIdx.y;
    const int b  = blockIdx.z;
    const int n0 = blockIdx.x * 64;

    const size_t base = ((size_t)b * D_MODEL + h) * N_SEQ;
    const float* qb = Q + base;
    const float* kb = K + base;
    const float* vb = V + base;

    {
        const int n   = t & 63;
        const int dk0 = t >> 6;
#pragma unroll
        for (int p = 0; p < 16; ++p) {
            int dk = dk0 + p * 4;
            Qs[dk * 64 + n] = qb[(size_t)dk * 16 * N_SEQ + n0 + n];
        }
    }

    float o[4][4];
    float mrow[4], lrow[4];
#pragma unroll
    for (int i = 0; i < 4; ++i) {
        mrow[i] = -1e30f; lrow[i] = 0.f;
#pragma unroll
        for (int j = 0; j < 4; ++j) o[i][j] = 0.f;
    }

    for (int m0 = 0; m0 < N_SEQ; m0 += 64) {
        __syncthreads();
        {
            const int m   = t & 63;
            const int dk0 = t >> 6;
#pragma unroll
            for (int p = 0; p < 16; ++p) {
                int dk = dk0 + p * 4;
                size_t goff = (size_t)dk * 16 * N_SEQ + m0 + m;
                KPs[dk * 64 + m] = kb[goff];
                int c4 = (dk >> 2) ^ (m & 15);
                Vs[m * 64 + (c4 << 2) + (dk & 3)] = vb[goff];
            }
        }
        __syncthreads();

        float s[4][4];
#pragma unroll
        for (int i = 0; i < 4; ++i)
#pragma unroll
            for (int j = 0; j < 4; ++j) s[i][j] = 0.f;

#pragma unroll 8
        for (int dk = 0; dk < 64; ++dk) {
            float4 a  = *(const float4*)&Qs[dk * 64 + 4 * ty];
            float4 bb = *(const float4*)&KPs[dk * 64 + 4 * tx];
            s[0][0] = fmaf(a.x, bb.x, s[0][0]); s[0][1] = fmaf(a.x, bb.y, s[0][1]);
            s[0][2] = fmaf(a.x, bb.z, s[0][2]); s[0][3] = fmaf(a.x, bb.w, s[0][3]);
            s[1][0] = fmaf(a.y, bb.x, s[1][0]); s[1][1] = fmaf(a.y, bb.y, s[1][1]);
            s[1][2] = fmaf(a.y, bb.z, s[1][2]); s[1][3] = fmaf(a.y, bb.w, s[1][3]);
            s[2][0] = fmaf(a.z, bb.x, s[2][0]); s[2][1] = fmaf(a.z, bb.y, s[2][1]);
            s[2][2] = fmaf(a.z, bb.z, s[2][2]); s[2][3] = fmaf(a.z, bb.w, s[2][3]);
            s[3][0] = fmaf(a.w, bb.x, s[3][0]); s[3][1] = fmaf(a.w, bb.y, s[3][1]);
            s[3][2] = fmaf(a.w, bb.z, s[3][2]); s[3][3] = fmaf(a.w, bb.w, s[3][3]);
        }

        float alpha[4];
#pragma unroll
        for (int i = 0; i < 4; ++i) {
#pragma unroll
            for (int j = 0; j < 4; ++j) s[i][j] *= 0.125f;
            float mx = fmaxf(fmaxf(s[i][0], s[i][1]), fmaxf(s[i][2], s[i][3]));
            mx = fmaxf(mx, __shfl_xor_sync(0xffffffffu, mx, 1));
            mx = fmaxf(mx, __shfl_xor_sync(0xffffffffu, mx, 2));
            mx = fmaxf(mx, __shfl_xor_sync(0xffffffffu, mx, 4));
            mx = fmaxf(mx, __shfl_xor_sync(0xffffffffu, mx, 8));
            float mn = fmaxf(mrow[i], mx);
            alpha[i] = __expf(mrow[i] - mn);
            mrow[i] = mn;
            float rs = 0.f;
#pragma unroll
            for (int j = 0; j < 4; ++j) { s[i][j] = __expf(s[i][j] - mn); rs += s[i][j]; }
            rs += __shfl_xor_sync(0xffffffffu, rs, 1);
            rs += __shfl_xor_sync(0xffffffffu, rs, 2);
            rs += __shfl_xor_sync(0xffffffffu, rs, 4);
            rs += __shfl_xor_sync(0xffffffffu, rs, 8);
            lrow[i] = lrow[i] * alpha[i] + rs;
#pragma unroll
            for (int j = 0; j < 4; ++j) o[i][j] *= alpha[i];
        }

        __syncthreads();
#pragma unroll
        for (int i = 0; i < 4; ++i)
            *(float4*)&KPs[(4 * ty + i) * 64 + 4 * tx] =
                make_float4(s[i][0], s[i][1], s[i][2], s[i][3]);
        __syncthreads();

#pragma unroll 4
        for (int c = 0; c < 64; ++c) {
            float4 vv = *(const float4*)&Vs[c * 64 + ((tx ^ (c & 15)) << 2)];
            float p0 = KPs[(4 * ty + 0) * 64 + c];
            float p1 = KPs[(4 * ty + 1) * 64 + c];
            float p2 = KPs[(4 * ty + 2) * 64 + c];
            float p3 = KPs[(4 * ty + 3) * 64 + c];
            o[0][0] = fmaf(p0, vv.x, o[0][0]); o[0][1] = fmaf(p0, vv.y, o[0][1]);
            o[0][2] = fmaf(p0, vv.z, o[0][2]); o[0][3] = fmaf(p0, vv.w, o[0][3]);
            o[1][0] = fmaf(p1, vv.x, o[1][0]); o[1][1] = fmaf(p1, vv.y, o[1][1]);
            o[1][2] = fmaf(p1, vv.z, o[1][2]); o[1][3] = fmaf(p1, vv.w, o[1][3]);
            o[2][0] = fmaf(p2, vv.x, o[2][0]); o[2][1] = fmaf(p2, vv.y, o[2][1]);
            o[2][2] = fmaf(p2, vv.z, o[2][2]); o[2][3] = fmaf(p2, vv.w, o[2][3]);
            o[3][0] = fmaf(p3, vv.x, o[3][0]); o[3][1] = fmaf(p3, vv.y, o[3][1]);
            o[3][2] = fmaf(p3, vv.z, o[3][2]); o[3][3] = fmaf(p3, vv.w, o[3][3]);
        }
    }

#pragma unroll
    for (int i = 0; i < 4; ++i) {
        float inv = 1.f / lrow[i];
#pragma unroll
        for (int j = 0; j < 4; ++j) {
            int dk = 4 * tx + j;
            O[base + (size_t)dk * 16 * N_SEQ + (n0 + 4 * ty + i)] = o[i][j] * inv;
        }
    }
}

// ---------------------------------------------------------------------------------------
extern "C" void kernel_launch(void* const* d_in, const int* in_sizes, int n_in,
                              void* d_out, int out_size)
{
    (void)in_sizes; (void)n_in; (void)out_size;
    const float* motion = (const float*)d_in[0];
    const float* Wq  = (const float*)d_in[1];
    const float* bq  = (const float*)d_in[2];
    const float* Wk  = (const float*)d_in[3];
    const float* bk  = (const float*)d_in[4];
    const float* Wv  = (const float*)d_in[5];
    const float* bv  = (const float*)d_in[6];
    const float* Wm  = (const float*)d_in[7];
    const float* bm  = (const float*)d_in[8];
    const float* Wp1 = (const float*)d_in[9];
    const float* bp1 = (const float*)d_in[10];
    const float* bng = (const float*)d_in[11];
    const float* bnb = (const float*)d_in[12];
    const float* bnm = (const float*)d_in[13];
    const float* bnv = (const float*)d_in[14];
    const float* Wp2 = (const float*)d_in[15];
    const float* bp2 = (const float*)d_in[16];

    float *qb, *kb, *vb, *ab, *mb, *hb, *xb;
    cudaGetSymbolAddress((void**)&qb, g_q);
    cudaGetSymbolAddress((void**)&kb, g_k);
    cudaGetSymbolAddress((void**)&vb, g_v);
    cudaGetSymbolAddress((void**)&ab, g_a);
    cudaGetSymbolAddress((void**)&mb, g_m);
    cudaGetSymbolAddress((void**)&hb, g_h);
    cudaGetSymbolAddress((void**)&xb, g_x);

    dim3 blk(256);
    dim3 gP (N_SEQ / 128, D_MODEL / 128, B_BATCH);          // (8, 8, 4)
    dim3 gP1(N_SEQ / 128, (2 * D_MODEL) / 128, B_BATCH);    // (8, 16, 4)
    dim3 gA (N_SEQ / 64, H_HEADS, B_BATCH);                 // (16, 16, 4)

    for (int l = 0; l < 4; ++l) {
        const float* x   = (l == 0) ? motion : xb;
        float*       out = (l == 3) ? (float*)d_out : xb;
        const size_t wo  = (size_t)l * D_MODEL * D_MODEL;
        const size_t bo  = (size_t)l * D_MODEL;
        const size_t wo1 = (size_t)l * 4 * D_MODEL * D_MODEL;
        const size_t bo1 = (size_t)l * 2 * D_MODEL;
        const size_t wo2 = (size_t)l * 2 * D_MODEL * D_MODEL;

        gemm_tc<0><<<gP, blk>>>(Wq + wo, bq + bo, x, D_MODEL, nullptr,
                                nullptr, nullptr, nullptr, nullptr, nullptr,
                                qb, D_MODEL, D_MODEL);
        gemm_tc<0><<<gP, blk>>>(Wk + wo, bk + bo, x, D_MODEL, nullptr,
                                nullptr, nullptr, nullptr, nullptr, nullptr,
                                kb, D_MODEL, D_MODEL);
        gemm_tc<0><<<gP, blk>>>(Wv + wo, bv + bo, x, D_MODEL, nullptr,
                                nullptr, nullptr, nullptr, nullptr, nullptr,
                                vb, D_MODEL, D_MODEL);
        attn_k<<<gA, blk>>>(qb, kb, vb, ab);
        gemm_tc<0><<<gP, blk>>>(Wm + wo, bm + bo, ab, D_MODEL, nullptr,
                                nullptr, nullptr, nullptr, nullptr, nullptr,
                                mb, D_MODEL, D_MODEL);
        // p1: input = concat([merged, x]) read in-place; epilogue = BN(eval) + ReLU
        gemm_tc<1><<<gP1, blk>>>(Wp1 + wo1, bp1 + bo1, mb, D_MODEL, x,
                                 bng + bo1, bnb + bo1, bnm + bo1, bnv + bo1, nullptr,
                                 hb, 2 * D_MODEL, 2 * D_MODEL);
        // p2: epilogue = + residual x; last layer writes d_out directly
        gemm_tc<2><<<gP, blk>>>(Wp2 + wo2, bp2 + bo, hb, 2 * D_MODEL, nullptr,
                                nullptr, nullptr, nullptr, nullptr, x,
                                out, D_MODEL, 2 * D_MODEL);
    }
}

// round 4
// speedup vs baseline: 2.6440x; 1.3084x over previous
#include <cuda_runtime.h>
#include <cstdint>

#define D_MODEL 1024
#define N_SEQ   1024
#define B_BATCH 4
#define H_HEADS 16
// DK = 64

// ---------------- scratch (static device globals; no runtime allocation) ----------------
__device__ float g_q[(size_t)B_BATCH * D_MODEL * N_SEQ];
__device__ float g_k[(size_t)B_BATCH * D_MODEL * N_SEQ];
__device__ float g_v[(size_t)B_BATCH * D_MODEL * N_SEQ];
__device__ float g_a[(size_t)B_BATCH * D_MODEL * N_SEQ];
__device__ float g_m[(size_t)B_BATCH * D_MODEL * N_SEQ];
__device__ float g_h[(size_t)B_BATCH * 2 * D_MODEL * N_SEQ];
__device__ float g_x[(size_t)B_BATCH * D_MODEL * N_SEQ];

// ---------------------------------------------------------------------------------------
// TF32 helpers
// ---------------------------------------------------------------------------------------
__device__ __forceinline__ uint32_t f2tf32(float x) {
    uint32_t r;
    asm("cvt.rna.tf32.f32 %0, %1;" : "=r"(r) : "f"(x));
    return r;
}

__device__ __forceinline__ void mma_tf32(float& c0, float& c1, float& c2, float& c3,
                                         uint32_t a0, uint32_t a1, uint32_t a2, uint32_t a3,
                                         uint32_t b0, uint32_t b1) {
    asm volatile(
        "mma.sync.aligned.m16n8k8.row.col.f32.tf32.tf32.f32 "
        "{%0,%1,%2,%3}, {%4,%5,%6,%7}, {%8,%9}, {%0,%1,%2,%3};"
        : "+f"(c0), "+f"(c1), "+f"(c2), "+f"(c3)
        : "r"(a0), "r"(a1), "r"(a2), "r"(a3), "r"(b0), "r"(b1));
}

// ---------------------------------------------------------------------------------------
// TF32 tensor-core batched GEMM (unchanged from R3).
// ---------------------------------------------------------------------------------------
#define SROW 136

template<int EPI>
__global__ __launch_bounds__(256, 2)
void gemm_tc(const float* __restrict__ W, const float* __restrict__ bias,
             const float* __restrict__ X0, int rows0,
             const float* __restrict__ X1,
             const float* __restrict__ bng, const float* __restrict__ bnb,
             const float* __restrict__ bnm, const float* __restrict__ bnv,
             const float* __restrict__ res,
             float* __restrict__ Y, int Co, int Ci)
{
    __shared__ __align__(16) uint32_t As[2][16 * SROW];
    __shared__ __align__(16) uint32_t Bs[2][16 * SROW];

    const int t    = threadIdx.x;
    const int lane = t & 31;
    const int warp = t >> 5;
    const int wm   = warp & 1;
    const int wn   = warp >> 1;
    const int l4   = lane & 3;
    const int lg   = lane >> 2;
    const int b    = blockIdx.z;
    const int bm0  = blockIdx.y * 128;
    const int bn0  = blockIdx.x * 128;

    const int a_r  = t >> 1;
    const int a_kk = t & 1;
    const float* wptr = W + (size_t)(bm0 + a_r) * Ci + a_kk * 8;

    const int b_k   = t >> 4;
    const int b_ni  = t & 15;
    const int rows1 = Ci - rows0;

    float acc[4][4][4];
#pragma unroll
    for (int mi = 0; mi < 4; ++mi)
#pragma unroll
        for (int ni = 0; ni < 4; ++ni)
#pragma unroll
            for (int r = 0; r < 4; ++r) acc[mi][ni][r] = 0.f;

    float4 ra[2], rb[2];

    {
        ra[0] = *(const float4*)(wptr);
        ra[1] = *(const float4*)(wptr + 4);
        int ci = b_k;
        const float* src = (ci < rows0)
            ? (X0 + ((size_t)b * rows0 + ci) * N_SEQ)
            : (X1 + ((size_t)b * rows1 + (ci - rows0)) * N_SEQ);
        rb[0] = *(const float4*)(src + bn0 + b_ni * 8);
        rb[1] = *(const float4*)(src + bn0 + b_ni * 8 + 4);
    }

    int buf = 0;
    for (int kt = 0; kt < Ci; kt += 16) {
        {
            uint32_t* ad = &As[buf][0] + (a_kk * 8) * SROW + a_r;
            ad[0 * SROW] = f2tf32(ra[0].x);
            ad[1 * SROW] = f2tf32(ra[0].y);
            ad[2 * SROW] = f2tf32(ra[0].z);
            ad[3 * SROW] = f2tf32(ra[0].w);
            ad[4 * SROW] = f2tf32(ra[1].x);
            ad[5 * SROW] = f2tf32(ra[1].y);
            ad[6 * SROW] = f2tf32(ra[1].z);
            ad[7 * SROW] = f2tf32(ra[1].w);
            uint32_t* bd = &Bs[buf][0] + b_k * SROW + b_ni * 8;
            uint4 p0, p1;
            p0.x = f2tf32(rb[0].x); p0.y = f2tf32(rb[0].y);
            p0.z = f2tf32(rb[0].z); p0.w = f2tf32(rb[0].w);
            p1.x = f2tf32(rb[1].x); p1.y = f2tf32(rb[1].y);
            p1.z = f2tf32(rb[1].z); p1.w = f2tf32(rb[1].w);
            *(uint4*)(bd)     = p0;
            *(uint4*)(bd + 4) = p1;
        }
        __syncthreads();

        if (kt + 16 < Ci) {
            ra[0] = *(const float4*)(wptr + kt + 16);
            ra[1] = *(const float4*)(wptr + kt + 16 + 4);
            int ci = kt + 16 + b_k;
            const float* src = (ci < rows0)
                ? (X0 + ((size_t)b * rows0 + ci) * N_SEQ)
                : (X1 + ((size_t)b * rows1 + (ci - rows0)) * N_SEQ);
            rb[0] = *(const float4*)(src + bn0 + b_ni * 8);
            rb[1] = *(const float4*)(src + bn0 + b_ni * 8 + 4);
        }

        const uint32_t* Ab = &As[buf][0];
        const uint32_t* Bb = &Bs[buf][0];
#pragma unroll
        for (int kk = 0; kk < 2; ++kk) {
            const int a_off = (kk * 8 + l4) * SROW + wm * 64 + lg;
            const int b_off = (kk * 8 + l4) * SROW + wn * 32 + lg;
            uint32_t af[4][4];
            uint32_t bf[4][2];
#pragma unroll
            for (int mi = 0; mi < 4; ++mi) {
                af[mi][0] = Ab[a_off + mi * 16];
                af[mi][1] = Ab[a_off + mi * 16 + 8];
                af[mi][2] = Ab[a_off + mi * 16 + 4 * SROW];
                af[mi][3] = Ab[a_off + mi * 16 + 4 * SROW + 8];
            }
#pragma unroll
            for (int ni = 0; ni < 4; ++ni) {
                bf[ni][0] = Bb[b_off + ni * 8];
                bf[ni][1] = Bb[b_off + ni * 8 + 4 * SROW];
            }
#pragma unroll
            for (int mi = 0; mi < 4; ++mi)
#pragma unroll
                for (int ni = 0; ni < 4; ++ni)
                    mma_tf32(acc[mi][ni][0], acc[mi][ni][1], acc[mi][ni][2], acc[mi][ni][3],
                             af[mi][0], af[mi][1], af[mi][2], af[mi][3],
                             bf[ni][0], bf[ni][1]);
        }
        buf ^= 1;
    }

    const int g  = lane >> 2;
    const int tt = lane & 3;
#pragma unroll
    for (int mi = 0; mi < 4; ++mi) {
        const int r0 = bm0 + wm * 64 + mi * 16 + g;
        const int r1 = r0 + 8;
        float sc0 = 1.f, sh0, sc1 = 1.f, sh1;
        {
            float bv0 = bias[r0], bv1 = bias[r1];
            if (EPI == 1) {
                float s0 = bng[r0] * rsqrtf(bnv[r0] + 1e-5f);
                float s1 = bng[r1] * rsqrtf(bnv[r1] + 1e-5f);
                sc0 = s0; sh0 = (bv0 - bnm[r0]) * s0 + bnb[r0];
                sc1 = s1; sh1 = (bv1 - bnm[r1]) * s1 + bnb[r1];
            } else {
                sh0 = bv0; sh1 = bv1;
            }
        }
        float* y0 = Y + ((size_t)b * Co + r0) * N_SEQ;
        float* y1 = Y + ((size_t)b * Co + r1) * N_SEQ;
        const float* rr0 = (EPI == 2) ? (res + ((size_t)b * Co + r0) * N_SEQ) : nullptr;
        const float* rr1 = (EPI == 2) ? (res + ((size_t)b * Co + r1) * N_SEQ) : nullptr;
#pragma unroll
        for (int ni = 0; ni < 4; ++ni) {
            const int col = bn0 + wn * 32 + ni * 8 + 2 * tt;
            float v0 = acc[mi][ni][0], v1 = acc[mi][ni][1];
            float v2 = acc[mi][ni][2], v3 = acc[mi][ni][3];
            if (EPI == 1) {
                v0 = fmaxf(v0 * sc0 + sh0, 0.f);
                v1 = fmaxf(v1 * sc0 + sh0, 0.f);
                v2 = fmaxf(v2 * sc1 + sh1, 0.f);
                v3 = fmaxf(v3 * sc1 + sh1, 0.f);
            } else if (EPI == 2) {
                float2 q0 = *(const float2*)(rr0 + col);
                float2 q1 = *(const float2*)(rr1 + col);
                v0 += sh0 + q0.x; v1 += sh0 + q0.y;
                v2 += sh1 + q1.x; v3 += sh1 + q1.y;
            } else {
                v0 += sh0; v1 += sh0; v2 += sh1; v3 += sh1;
            }
            *(float2*)(y0 + col) = make_float2(v0, v1);
            *(float2*)(y1 + col) = make_float2(v2, v3);
        }
    }
}

// ---------------------------------------------------------------------------------------
// TF32 tensor-core flash attention. Layouts: Q/K/V/O are (B, D, N), channel = dk*16 + h.
// Block = 128 thr / 4 warps, one (b, h, 64-query tile); key chunks of 32.
// Phase 1 (S = Q^T K): warp owns 16 queries. Q A-frags from gmem (regs, loaded once),
//   K in smem Ks[dk][key] stride 40 (frag banks 8*tt+g: conflict-free).
// Softmax in exp2 domain (score scale folded into SC), quad shuffles.
// Phase 2 (O^T = V^T P^T): warp owns 16 dk rows. V A-frags direct from gmem layout (no
//   transpose needed!), P via smem Ps[q][key] stride 36 (banks 4*g+tt: conflict-free).
//   Per-query alpha/l broadcast through smem. O stored transposed = gmem layout.
// ---------------------------------------------------------------------------------------
__global__ __launch_bounds__(128)
void attn_tc(const float* __restrict__ Q, const float* __restrict__ K,
             const float* __restrict__ V, float* __restrict__ O)
{
    __shared__ __align__(16) uint32_t Ks[64 * 40];
    __shared__ __align__(16) uint32_t Ps[64 * 36];
    __shared__ float alphas[64];
    __shared__ float ls[64];

    const int t    = threadIdx.x;
    const int lane = t & 31;
    const int warp = t >> 5;
    const int g    = lane >> 2;
    const int tt   = lane & 3;
    const int h    = blockIdx.y;
    const int b    = blockIdx.z;
    const int n0   = blockIdx.x * 64;
    const int qw   = warp * 16;   // phase-1 query base
    const int dkw  = warp * 16;   // phase-2 dk base
    const int CH   = H_HEADS * N_SEQ;  // channel stride

    const size_t base = ((size_t)b * D_MODEL + h) * N_SEQ;
    const float* qb = Q + base;
    const float* kb = K + base;
    const float* vb = V + base;

    // Q fragments (registers, whole kernel): a0=(q g, dk tt) a1=(q g+8) a2=(dk tt+4) a3=both
    uint32_t aq[8][4];
#pragma unroll
    for (int ks = 0; ks < 8; ++ks) {
        const float* q0 = qb + (size_t)(ks * 8 + tt) * CH + n0 + qw + g;
        const float* q1 = qb + (size_t)(ks * 8 + tt + 4) * CH + n0 + qw + g;
        aq[ks][0] = f2tf32(q0[0]);
        aq[ks][1] = f2tf32(q0[8]);
        aq[ks][2] = f2tf32(q1[0]);
        aq[ks][3] = f2tf32(q1[8]);
    }

    const float SC = 0.125f * 1.44269504089f;  // score scale * log2(e)
    float m2a = -1e30f, m2b = -1e30f;          // running max (exp2 domain)
    float la = 0.f, lb = 0.f;                  // running denominators
    float o[8][4];
#pragma unroll
    for (int nq = 0; nq < 8; ++nq)
#pragma unroll
        for (int r = 0; r < 4; ++r) o[nq][r] = 0.f;

    for (int m0 = 0; m0 < N_SEQ; m0 += 32) {
        // ---- load K chunk -> smem (tf32) ----
#pragma unroll
        for (int j = 0; j < 4; ++j) {
            int id = t + 128 * j;
            int dk = id >> 3, m4 = (id & 7) * 4;
            float4 kv = *(const float4*)(kb + (size_t)dk * CH + m0 + m4);
            uint4 pk;
            pk.x = f2tf32(kv.x); pk.y = f2tf32(kv.y);
            pk.z = f2tf32(kv.z); pk.w = f2tf32(kv.w);
            *(uint4*)&Ks[dk * 40 + m4] = pk;
        }
        __syncthreads();

        // ---- S = Q^T K : s[ni] covers keys ni*8..ni*8+7 ----
        float s[4][4];
#pragma unroll
        for (int ni = 0; ni < 4; ++ni)
#pragma unroll
            for (int r = 0; r < 4; ++r) s[ni][r] = 0.f;
#pragma unroll
        for (int ks = 0; ks < 8; ++ks) {
            const uint32_t* kr0 = &Ks[(ks * 8 + tt) * 40 + g];
            const uint32_t* kr1 = &Ks[(ks * 8 + tt + 4) * 40 + g];
#pragma unroll
            for (int ni = 0; ni < 4; ++ni)
                mma_tf32(s[ni][0], s[ni][1], s[ni][2], s[ni][3],
                         aq[ks][0], aq[ks][1], aq[ks][2], aq[ks][3],
                         kr0[ni * 8], kr1[ni * 8]);
        }

        // ---- online softmax (rows qw+g, qw+g+8) ----
        float mx0 = s[0][0], mx1 = s[0][2];
#pragma unroll
        for (int ni = 0; ni < 4; ++ni) {
            mx0 = fmaxf(mx0, fmaxf(s[ni][0], s[ni][1]));
            mx1 = fmaxf(mx1, fmaxf(s[ni][2], s[ni][3]));
        }
        mx0 = fmaxf(mx0, __shfl_xor_sync(0xffffffffu, mx0, 1));
        mx0 = fmaxf(mx0, __shfl_xor_sync(0xffffffffu, mx0, 2));
        mx1 = fmaxf(mx1, __shfl_xor_sync(0xffffffffu, mx1, 1));
        mx1 = fmaxf(mx1, __shfl_xor_sync(0xffffffffu, mx1, 2));
        float mn0 = fmaxf(m2a, mx0 * SC);
        float mn1 = fmaxf(m2b, mx1 * SC);
        float alpha0 = exp2f(m2a - mn0);
        float alpha1 = exp2f(m2b - mn1);
        m2a = mn0; m2b = mn1;
        float rs0 = 0.f, rs1 = 0.f;
#pragma unroll
        for (int ni = 0; ni < 4; ++ni) {
            s[ni][0] = exp2f(fmaf(s[ni][0], SC, -mn0));
            s[ni][1] = exp2f(fmaf(s[ni][1], SC, -mn0));
            s[ni][2] = exp2f(fmaf(s[ni][2], SC, -mn1));
            s[ni][3] = exp2f(fmaf(s[ni][3], SC, -mn1));
            rs0 += s[ni][0] + s[ni][1];
            rs1 += s[ni][2] + s[ni][3];
        }
        rs0 += __shfl_xor_sync(0xffffffffu, rs0, 1);
        rs0 += __shfl_xor_sync(0xffffffffu, rs0, 2);
        rs1 += __shfl_xor_sync(0xffffffffu, rs1, 1);
        rs1 += __shfl_xor_sync(0xffffffffu, rs1, 2);
        la = la * alpha0 + rs0;
        lb = lb * alpha1 + rs1;

        // ---- write P (tf32) + alphas ----
#pragma unroll
        for (int ni = 0; ni < 4; ++ni) {
            uint2 p0, p1;
            p0.x = f2tf32(s[ni][0]); p0.y = f2tf32(s[ni][1]);
            p1.x = f2tf32(s[ni][2]); p1.y = f2tf32(s[ni][3]);
            *(uint2*)&Ps[(qw + g) * 36 + ni * 8 + 2 * tt]     = p0;
            *(uint2*)&Ps[(qw + g + 8) * 36 + ni * 8 + 2 * tt] = p1;
        }
        if (tt == 0) {
            alphas[qw + g]     = alpha0;
            alphas[qw + g + 8] = alpha1;
        }
        __syncthreads();

        // ---- phase 2: O^T[dk 16][q 64] += V^T P^T ----
#pragma unroll
        for (int nq = 0; nq < 8; ++nq) {
            float2 al = *(const float2*)&alphas[nq * 8 + 2 * tt];
            o[nq][0] *= al.x; o[nq][1] *= al.y;
            o[nq][2] *= al.x; o[nq][3] *= al.y;
        }
        const float* v0p = vb + (size_t)(dkw + g) * CH + m0;
        const float* v1p = vb + (size_t)(dkw + g + 8) * CH + m0;
#pragma unroll
        for (int ks = 0; ks < 4; ++ks) {
            const int c = ks * 8 + tt;
            uint32_t va0 = f2tf32(v0p[c]);
            uint32_t va1 = f2tf32(v1p[c]);
            uint32_t va2 = f2tf32(v0p[c + 4]);
            uint32_t va3 = f2tf32(v1p[c + 4]);
#pragma unroll
            for (int nq = 0; nq < 8; ++nq) {
                uint32_t b0 = Ps[(nq * 8 + g) * 36 + c];
                uint32_t b1 = Ps[(nq * 8 + g) * 36 + c + 4];
                mma_tf32(o[nq][0], o[nq][1], o[nq][2], o[nq][3],
                         va0, va1, va2, va3, b0, b1);
            }
        }
        __syncthreads();
    }

    if (tt == 0) { ls[qw + g] = la; ls[qw + g + 8] = lb; }
    __syncthreads();

    // ---- normalize + write O (already in gmem layout) ----
#pragma unroll
    for (int nq = 0; nq < 8; ++nq) {
        float2 lv = *(const float2*)&ls[nq * 8 + 2 * tt];
        float i0 = 1.f / lv.x, i1 = 1.f / lv.y;
        float* o0 = O + base + (size_t)(dkw + g) * CH + n0 + nq * 8 + 2 * tt;
        float* o1 = O + base + (size_t)(dkw + g + 8) * CH + n0 + nq * 8 + 2 * tt;
        *(float2*)o0 = make_float2(o[nq][0] * i0, o[nq][1] * i1);
        *(float2*)o1 = make_float2(o[nq][2] * i0, o[nq][3] * i1);
    }
}

// ---------------------------------------------------------------------------------------
extern "C" void kernel_launch(void* const* d_in, const int* in_sizes, int n_in,
                              void* d_out, int out_size)
{
    (void)in_sizes; (void)n_in; (void)out_size;
    const float* motion = (const float*)d_in[0];
    const float* Wq  = (const float*)d_in[1];
    const float* bq  = (const float*)d_in[2];
    const float* Wk  = (const float*)d_in[3];
    const float* bk  = (const float*)d_in[4];
    const float* Wv  = (const float*)d_in[5];
    const float* bv  = (const float*)d_in[6];
    const float* Wm  = (const float*)d_in[7];
    const float* bm  = (const float*)d_in[8];
    const float* Wp1 = (const float*)d_in[9];
    const float* bp1 = (const float*)d_in[10];
    const float* bng = (const float*)d_in[11];
    const float* bnb = (const float*)d_in[12];
    const float* bnm = (const float*)d_in[13];
    const float* bnv = (const float*)d_in[14];
    const float* Wp2 = (const float*)d_in[15];
    const float* bp2 = (const float*)d_in[16];

    float *qb, *kb, *vb, *ab, *mb, *hb, *xb;
    cudaGetSymbolAddress((void**)&qb, g_q);
    cudaGetSymbolAddress((void**)&kb, g_k);
    cudaGetSymbolAddress((void**)&vb, g_v);
    cudaGetSymbolAddress((void**)&ab, g_a);
    cudaGetSymbolAddress((void**)&mb, g_m);
    cudaGetSymbolAddress((void**)&hb, g_h);
    cudaGetSymbolAddress((void**)&xb, g_x);

    dim3 blk(256);
    dim3 gP (N_SEQ / 128, D_MODEL / 128, B_BATCH);          // (8, 8, 4)
    dim3 gP1(N_SEQ / 128, (2 * D_MODEL) / 128, B_BATCH);    // (8, 16, 4)
    dim3 blkA(128);
    dim3 gA (N_SEQ / 64, H_HEADS, B_BATCH);                 // (16, 16, 4)

    for (int l = 0; l < 4; ++l) {
        const float* x   = (l == 0) ? motion : xb;
        float*       out = (l == 3) ? (float*)d_out : xb;
        const size_t wo  = (size_t)l * D_MODEL * D_MODEL;
        const size_t bo  = (size_t)l * D_MODEL;
        const size_t wo1 = (size_t)l * 4 * D_MODEL * D_MODEL;
        const size_t bo1 = (size_t)l * 2 * D_MODEL;
        const size_t wo2 = (size_t)l * 2 * D_MODEL * D_MODEL;

        gemm_tc<0><<<gP, blk>>>(Wq + wo, bq + bo, x, D_MODEL, nullptr,
                                nullptr, nullptr, nullptr, nullptr, nullptr,
                                qb, D_MODEL, D_MODEL);
        gemm_tc<0><<<gP, blk>>>(Wk + wo, bk + bo, x, D_MODEL, nullptr,
                                nullptr, nullptr, nullptr, nullptr, nullptr,
                                kb, D_MODEL, D_MODEL);
        gemm_tc<0><<<gP, blk>>>(Wv + wo, bv + bo, x, D_MODEL, nullptr,
                                nullptr, nullptr, nullptr, nullptr, nullptr,
                                vb, D_MODEL, D_MODEL);
        attn_tc<<<gA, blkA>>>(qb, kb, vb, ab);
        gemm_tc<0><<<gP, blk>>>(Wm + wo, bm + bo, ab, D_MODEL, nullptr,
                                nullptr, nullptr, nullptr, nullptr, nullptr,
                                mb, D_MODEL, D_MODEL);
        // p1: input = concat([merged, x]) read in-place; epilogue = BN(eval) + ReLU
        gemm_tc<1><<<gP1, blk>>>(Wp1 + wo1, bp1 + bo1, mb, D_MODEL, x,
                                 bng + bo1, bnb + bo1, bnm + bo1, bnv + bo1, nullptr,
                                 hb, 2 * D_MODEL, 2 * D_MODEL);
        // p2: epilogue = + residual x; last layer writes d_out directly
        gemm_tc<2><<<gP, blk>>>(Wp2 + wo2, bp2 + bo, hb, 2 * D_MODEL, nullptr,
                                nullptr, nullptr, nullptr, nullptr, x,
                                out, D_MODEL, 2 * D_MODEL);
    }
}